// round 4
// baseline (speedup 1.0000x reference)
#include <cuda_runtime.h>

// Ax[b,m,t] = sum_{c=0..7} x[b, m*8+c, t] * W[m,c]
// x: (16, 1024, 2048) f32, W: (128, 8) f32
// out: Ax (4194304 floats) then A_full (128*1024 floats).
// Each thread produces TWO float4 outputs (t4 and t4+256 of one channel row),
// giving 16 outstanding loads per thread. Grid covers all work exactly once.

#define B_ 16
#define M_ 128
#define C_ 8
#define T_ 2048
#define T4_ (T_ / 4)                   // 512 float4 per channel row
#define HALF_ (T4_ / 2)                // 256
#define AX_ELEMS (B_ * M_ * T_)        // 4194304
#define AX_VEC   (AX_ELEMS / 4)        // 1048576 float4
#define AX_PAIRS (AX_VEC / 2)          // 524288
#define AF_ELEMS (M_ * 1024)           // 131072
#define AF_VEC   (AF_ELEMS / 4)        // 32768 float4
#define AF_PAIRS (AF_VEC / 2)          // 16384
#define TOTAL_PAIRS (AX_PAIRS + AF_PAIRS)  // 540672

#define NTHREADS 256
#define NBLOCKS (TOTAL_PAIRS / NTHREADS)   // 2112, exact

__global__ void __launch_bounds__(NTHREADS)
fused_kernel(const float* __restrict__ x, const float* __restrict__ W,
             float* __restrict__ out)
{
    int pid = blockIdx.x * NTHREADS + threadIdx.x;

    if (pid < AX_PAIRS) {
        // ---- Ax path: two float4 outputs of one (b,m) row ----
        int t4 = pid & (HALF_ - 1);        // 0..255
        int m  = (pid >> 8) & (M_ - 1);    // 0..127
        int b  = pid >> 15;                // 0..15

        const float4* xb = (const float4*)(x + ((size_t)(b * 1024 + m * C_) * T_)) + t4;
        const float*  w  = W + m * C_;     // uniform within warp -> L1 broadcast

        // front-batch 16 loads (8 rows x 2 halves) for MLP
        float4 a0 = __ldcs(&xb[0 * T4_]);         float4 b0 = __ldcs(&xb[0 * T4_ + HALF_]);
        float4 a1 = __ldcs(&xb[1 * T4_]);         float4 b1 = __ldcs(&xb[1 * T4_ + HALF_]);
        float4 a2 = __ldcs(&xb[2 * T4_]);         float4 b2 = __ldcs(&xb[2 * T4_ + HALF_]);
        float4 a3 = __ldcs(&xb[3 * T4_]);         float4 b3 = __ldcs(&xb[3 * T4_ + HALF_]);
        float4 a4 = __ldcs(&xb[4 * T4_]);         float4 b4 = __ldcs(&xb[4 * T4_ + HALF_]);
        float4 a5 = __ldcs(&xb[5 * T4_]);         float4 b5 = __ldcs(&xb[5 * T4_ + HALF_]);
        float4 a6 = __ldcs(&xb[6 * T4_]);         float4 b6 = __ldcs(&xb[6 * T4_ + HALF_]);
        float4 a7 = __ldcs(&xb[7 * T4_]);         float4 b7 = __ldcs(&xb[7 * T4_ + HALF_]);

        float w0 = w[0], w1 = w[1], w2 = w[2], w3 = w[3];
        float w4 = w[4], w5 = w[5], w6 = w[6], w7 = w[7];

        float4 accA, accB;
        accA.x = a0.x * w0; accA.y = a0.y * w0; accA.z = a0.z * w0; accA.w = a0.w * w0;
        accB.x = b0.x * w0; accB.y = b0.y * w0; accB.z = b0.z * w0; accB.w = b0.w * w0;

#define STEP(av, bv, wc) \
        accA.x = fmaf(av.x, wc, accA.x); accA.y = fmaf(av.y, wc, accA.y); \
        accA.z = fmaf(av.z, wc, accA.z); accA.w = fmaf(av.w, wc, accA.w); \
        accB.x = fmaf(bv.x, wc, accB.x); accB.y = fmaf(bv.y, wc, accB.y); \
        accB.z = fmaf(bv.z, wc, accB.z); accB.w = fmaf(bv.w, wc, accB.w);

        STEP(a1, b1, w1)
        STEP(a2, b2, w2)
        STEP(a3, b3, w3)
        STEP(a4, b4, w4)
        STEP(a5, b5, w5)
        STEP(a6, b6, w6)
        STEP(a7, b7, w7)
#undef STEP

        int idx = (b << 16) | (m << 9) | t4;   // float4 index into Ax
        __stcs(&((float4*)out)[idx], accA);
        __stcs(&((float4*)out)[idx + HALF_], accB);
    } else {
        // ---- A_full: two float4 outputs ----
        int p = pid - AX_PAIRS;               // 0..AF_PAIRS-1
#pragma unroll
        for (int h = 0; h < 2; ++h) {
            int aidx = p + h * AF_PAIRS;      // 0..AF_VEC-1
            int row  = aidx >> 8;             // 256 float4 per 1024-col row
            int col0 = (aidx & 255) * 4;

            float4 v;
            float* vp = &v.x;
#pragma unroll
            for (int j = 0; j < 4; ++j) {
                int col = col0 + j;
                vp[j] = ((col >> 3) == row) ? W[row * C_ + (col & 7)] : 0.0f;
            }
            __stcs(&((float4*)(out + AX_ELEMS))[aidx], v);
        }
    }
}

extern "C" void kernel_launch(void* const* d_in, const int* in_sizes, int n_in,
                              void* d_out, int out_size)
{
    const float* x = (const float*)d_in[0];
    const float* W = (const float*)d_in[1];
    float* out = (float*)d_out;

    fused_kernel<<<NBLOCKS, NTHREADS>>>(x, W, out);
}

// round 6
// speedup vs baseline: 1.0168x; 1.0168x over previous
#include <cuda_runtime.h>

// Ax[b,m,t] = sum_{c=0..7} x[b, m*8+c, t] * W[m,c]
// x: (16, 1024, 2048) f32, W: (128, 8) f32
// out: Ax (4194304 floats) then A_full (128*1024 floats).
// Persistent one-wave grid (592 blocks = 148 SMs x 4 blocks), grid-stride over
// "pairs": each pair produces two float4 outputs (t4 and t4+256 of one
// (b,m) channel group), front-batching 16 loads for MLP.

#define B_ 16
#define M_ 128
#define C_ 8
#define T_ 2048
#define T4_ (T_ / 4)                   // 512 float4 per channel row
#define HALF_ (T4_ / 2)                // 256
#define AX_ELEMS (B_ * M_ * T_)        // 4194304
#define AX_VEC   (AX_ELEMS / 4)        // 1048576 float4
#define AX_PAIRS (AX_VEC / 2)          // 524288
#define AF_ELEMS (M_ * 1024)           // 131072
#define AF_VEC   (AF_ELEMS / 4)        // 32768 float4
#define AF_PAIRS (AF_VEC / 2)          // 16384
#define TOTAL_PAIRS (AX_PAIRS + AF_PAIRS)  // 540672

#define NTHREADS 256
#define NBLOCKS  592                   // 148 SMs * 4 resident blocks = 1 wave

__global__ void __launch_bounds__(NTHREADS)
fused_kernel(const float* __restrict__ x, const float* __restrict__ W,
             float* __restrict__ out)
{
    const int stride = NBLOCKS * NTHREADS;

    for (int pid = blockIdx.x * NTHREADS + threadIdx.x; pid < TOTAL_PAIRS; pid += stride) {
        if (pid < AX_PAIRS) {
            // ---- Ax path: two float4 outputs of one (b,m) channel group ----
            int t4 = pid & (HALF_ - 1);        // 0..255
            int m  = (pid >> 8) & (M_ - 1);    // 0..127
            int b  = pid >> 15;                // 0..15

            const float4* xb = (const float4*)(x + ((size_t)(b * 1024 + m * C_) * T_)) + t4;
            const float*  w  = W + m * C_;     // uniform within warp -> L1 broadcast

            // front-batch 16 loads (8 rows x 2 halves) for MLP
            float4 a0 = __ldcs(&xb[0 * T4_]);  float4 b0 = __ldcs(&xb[0 * T4_ + HALF_]);
            float4 a1 = __ldcs(&xb[1 * T4_]);  float4 b1 = __ldcs(&xb[1 * T4_ + HALF_]);
            float4 a2 = __ldcs(&xb[2 * T4_]);  float4 b2 = __ldcs(&xb[2 * T4_ + HALF_]);
            float4 a3 = __ldcs(&xb[3 * T4_]);  float4 b3 = __ldcs(&xb[3 * T4_ + HALF_]);
            float4 a4 = __ldcs(&xb[4 * T4_]);  float4 b4 = __ldcs(&xb[4 * T4_ + HALF_]);
            float4 a5 = __ldcs(&xb[5 * T4_]);  float4 b5 = __ldcs(&xb[5 * T4_ + HALF_]);
            float4 a6 = __ldcs(&xb[6 * T4_]);  float4 b6 = __ldcs(&xb[6 * T4_ + HALF_]);
            float4 a7 = __ldcs(&xb[7 * T4_]);  float4 b7 = __ldcs(&xb[7 * T4_ + HALF_]);

            float w0 = w[0], w1 = w[1], w2 = w[2], w3 = w[3];
            float w4 = w[4], w5 = w[5], w6 = w[6], w7 = w[7];

            float4 accA, accB;
            accA.x = a0.x * w0; accA.y = a0.y * w0; accA.z = a0.z * w0; accA.w = a0.w * w0;
            accB.x = b0.x * w0; accB.y = b0.y * w0; accB.z = b0.z * w0; accB.w = b0.w * w0;

#define STEP(av, bv, wc) \
            accA.x = fmaf(av.x, wc, accA.x); accA.y = fmaf(av.y, wc, accA.y); \
            accA.z = fmaf(av.z, wc, accA.z); accA.w = fmaf(av.w, wc, accA.w); \
            accB.x = fmaf(bv.x, wc, accB.x); accB.y = fmaf(bv.y, wc, accB.y); \
            accB.z = fmaf(bv.z, wc, accB.z); accB.w = fmaf(bv.w, wc, accB.w);

            STEP(a1, b1, w1)
            STEP(a2, b2, w2)
            STEP(a3, b3, w3)
            STEP(a4, b4, w4)
            STEP(a5, b5, w5)
            STEP(a6, b6, w6)
            STEP(a7, b7, w7)
#undef STEP

            int idx = (b << 16) | (m << 9) | t4;   // float4 index into Ax
            __stcs(&((float4*)out)[idx], accA);
            __stcs(&((float4*)out)[idx + HALF_], accB);
        } else {
            // ---- A_full: two float4 outputs ----
            int p = pid - AX_PAIRS;               // 0..AF_PAIRS-1
#pragma unroll
            for (int h = 0; h < 2; ++h) {
                int aidx = p + h * AF_PAIRS;      // 0..AF_VEC-1
                int row  = aidx >> 8;             // 256 float4 per 1024-col row
                int col0 = (aidx & 255) * 4;

                float4 v;
                float* vp = &v.x;
#pragma unroll
                for (int j = 0; j < 4; ++j) {
                    int col = col0 + j;
                    vp[j] = ((col >> 3) == row) ? W[row * C_ + (col & 7)] : 0.0f;
                }
                __stcs(&((float4*)(out + AX_ELEMS))[aidx], v);
            }
        }
    }
}

extern "C" void kernel_launch(void* const* d_in, const int* in_sizes, int n_in,
                              void* d_out, int out_size)
{
    const float* x = (const float*)d_in[0];
    const float* W = (const float*)d_in[1];
    float* out = (float*)d_out;

    fused_kernel<<<NBLOCKS, NTHREADS>>>(x, W, out);
}